// round 9
// baseline (speedup 1.0000x reference)
#include <cuda_runtime.h>

// out[i,p] = sum_{m,n} A[i,m] * B[i,n] * C[m,n,p]   (M1=M2=MP=5)
//
// Round-9 = round-8 (constant-bank C, float2 streaming IO, EPT=2) plus:
//  (1) C pad-transposed into constant as cCp[m][p][8] so each (m,p) column
//      is one LDC.128 + LDC.32 (2 issues instead of 5 scalar LDC; cuts ~75
//      issue slots/thread). Prep = tiny transpose kernel into a __device__
//      scratch + cudaMemcpyToSymbolAsync (both graph-capturable, no allocs).
//  (2) __launch_bounds__(256,5): 48-reg cap -> 5 CTAs/SM, 40 warps (+25%
//      latency coverage). Round-8 body's live set (~45 regs) fits.

#define M1 5
#define M2 5
#define MP 5
#define EPT 2
#define TPB 256
#define CPAD_FLOATS (M1 * MP * 8)      // 200

__constant__ float cCp[CPAD_FLOATS];   // cCp[(m*5+p)*8 + n], n in 0..4, padded
__device__ float g_scratch[CPAD_FLOATS];

__global__ void transpose_C_kernel(const float* __restrict__ C) {
    int idx = threadIdx.x;             // one block of 256 covers 200 slots
    if (idx < CPAD_FLOATS) {
        int m   = idx / (MP * 8);
        int rem = idx % (MP * 8);
        int p   = rem / 8;
        int n   = rem % 8;
        g_scratch[idx] = (n < M2) ? C[(m * M2 + n) * MP + p] : 0.0f;
    }
}

__global__ __launch_bounds__(TPB, 5)
void cg_combine_kernel(const float* __restrict__ A,
                       const float* __restrict__ B,
                       float* __restrict__ out,
                       long long n_edges)
{
    int t = threadIdx.x;
    long long tid = (long long)blockIdx.x * TPB + t;
    long long e0  = tid * EPT;

    if (e0 + EPT <= n_edges) {
        // ---- fast path: float2-vectorized streaming IO ----
        size_t baseA = (size_t)e0 * M1;
        size_t baseB = (size_t)e0 * M2;
        size_t baseO = (size_t)e0 * MP;

        float a[EPT * M1];   // [e0c0..e0c4, e1c0..e1c4]
        float b[EPT * M2];

        {
            const float2* A2 = reinterpret_cast<const float2*>(A + baseA);
            const float2* B2 = reinterpret_cast<const float2*>(B + baseB);
            float2 av[5], bv[5];
#pragma unroll
            for (int i = 0; i < 5; i++) { av[i] = __ldcs(A2 + i); bv[i] = __ldcs(B2 + i); }
#pragma unroll
            for (int i = 0; i < 5; i++) {
                a[i * 2 + 0] = av[i].x; a[i * 2 + 1] = av[i].y;
                b[i * 2 + 0] = bv[i].x; b[i * 2 + 1] = bv[i].y;
            }
        }

        float acc[EPT * MP];
#pragma unroll
        for (int i = 0; i < EPT * MP; i++) acc[i] = 0.0f;

#pragma unroll
        for (int m = 0; m < M1; m++) {
            float am0 = a[m];          // edge0 component m
            float am1 = a[M1 + m];     // edge1 component m
#pragma unroll
            for (int p = 0; p < MP; p++) {
                // C column (m, :, p): LDC.128 + LDC.32 from padded constant
                const float4 c03 =
                    *reinterpret_cast<const float4*>(&cCp[(m * MP + p) * 8]);
                const float  c4  = cCp[(m * MP + p) * 8 + 4];

                float d0 = c03.x * b[0];
                float d1 = c03.x * b[M2 + 0];
                d0 = fmaf(b[1],      c03.y, d0);
                d1 = fmaf(b[M2 + 1], c03.y, d1);
                d0 = fmaf(b[2],      c03.z, d0);
                d1 = fmaf(b[M2 + 2], c03.z, d1);
                d0 = fmaf(b[3],      c03.w, d0);
                d1 = fmaf(b[M2 + 3], c03.w, d1);
                d0 = fmaf(b[4],      c4,    d0);
                d1 = fmaf(b[M2 + 4], c4,    d1);

                acc[p]      = fmaf(am0, d0, acc[p]);
                acc[MP + p] = fmaf(am1, d1, acc[MP + p]);
            }
        }

        {
            float2* O2 = reinterpret_cast<float2*>(out + baseO);
            float2 ov[5];
#pragma unroll
            for (int i = 0; i < 5; i++) {
                ov[i].x = acc[i * 2 + 0];
                ov[i].y = acc[i * 2 + 1];
            }
#pragma unroll
            for (int i = 0; i < 5; i++) __stcs(O2 + i, ov[i]);
        }
    } else if (e0 < n_edges) {
        // ---- tail path (scalar; not taken for N = 16,777,216) ----
        for (long long e = e0; e < n_edges; e++) {
            float a[M1], b[M2];
#pragma unroll
            for (int k = 0; k < 5; k++) { a[k] = A[e * 5 + k]; b[k] = B[e * 5 + k]; }
#pragma unroll
            for (int p = 0; p < MP; p++) {
                float s = 0.0f;
#pragma unroll
                for (int m = 0; m < M1; m++) {
                    float d = 0.0f;
#pragma unroll
                    for (int n = 0; n < M2; n++)
                        d = fmaf(b[n], cCp[(m * MP + p) * 8 + n], d);
                    s = fmaf(a[m], d, s);
                }
                out[e * 5 + p] = s;
            }
        }
    }
}

extern "C" void kernel_launch(void* const* d_in, const int* in_sizes, int n_in,
                              void* d_out, int out_size)
{
    const float* A = (const float*)d_in[0];
    const float* B = (const float*)d_in[1];
    const float* C = (const float*)d_in[2];
    float* out = (float*)d_out;

    // Prep: pad-transpose C into __device__ scratch, then copy into the
    // constant bank. Both are graph-capturable nodes on stream 0; stream
    // order guarantees the main kernel sees the finished constant data.
    transpose_C_kernel<<<1, TPB>>>(C);
    void* scratch_ptr = nullptr;
    cudaGetSymbolAddress(&scratch_ptr, g_scratch);
    cudaMemcpyToSymbolAsync(cCp, scratch_ptr, CPAD_FLOATS * sizeof(float), 0,
                            cudaMemcpyDeviceToDevice, 0);

    long long n_edges = (long long)in_sizes[0] / M1;
    long long n_threads = (n_edges + EPT - 1) / EPT;
    int blocks = (int)((n_threads + TPB - 1) / TPB);

    cg_combine_kernel<<<blocks, TPB>>>(A, B, out, n_edges);
}